// round 2
// baseline (speedup 1.0000x reference)
#include <cuda_runtime.h>
#include <cuda_bf16.h>
#include <stdint.h>

// Problem constants
#define BB 64
#define TT 512
#define UU 256
#define PITCH 264   // bf16 elems per smem/global row: 256 + 8 pad (16B) -> conflict-free LDS.128

// Scratch (no allocation allowed): precomputed exp(trans)-1, transposed; per-batch ll
__device__ __nv_bfloat16 g_em1t[UU * PITCH];
__device__ float g_ll[BB];

// ---------------------------------------------------------------------------
// Kernel 0: Em1t[u][v] = exp(trans[v][u]) - 1  (bf16, transposed, padded rows)
// ---------------------------------------------------------------------------
__global__ void k_prep(const float* __restrict__ trans) {
    int u = blockIdx.x;   // destination tag (row of transposed matrix)
    int v = threadIdx.x;  // source tag
    float e = __expf(trans[v * UU + u]) - 1.0f;
    g_em1t[u * PITCH + v] = __float2bfloat16(e);
}

// ---------------------------------------------------------------------------
// Kernel 1: per-batch CRF forward + path score. One CTA per batch, thread = u.
// ---------------------------------------------------------------------------
__global__ __launch_bounds__(256, 1) void k_forward(
    const float* __restrict__ pot,     // [B,T,U]
    const int*   __restrict__ tags,    // [B,T]
    const int*   __restrict__ seqlen,  // [B]
    const float* __restrict__ trans)   // [U,U]
{
    extern __shared__ char smem_raw[];
    __nv_bfloat16* Es   = (__nv_bfloat16*)smem_raw;               // UU*PITCH bf16
    float* ea     = (float*)(smem_raw + UU * PITCH * 2);          // 256 f32 (16B aligned)
    float* red    = ea + UU;                                      // 8
    float* cscale = red + 8;                                      // 1
    float* sscore = cscale + 1;                                   // 1

    const int b    = blockIdx.x;
    const int u    = threadIdx.x;
    const int wid  = u >> 5;
    const int lane = u & 31;
    const int L    = seqlen[b];

    // ---- stage Em1t into shared memory (135168 B as uint4) ----
    {
        const uint4* src = (const uint4*)g_em1t;
        uint4*       dst = (uint4*)Es;
        const int n = UU * PITCH * 2 / 16;   // 8448
        #pragma unroll 4
        for (int i = u; i < n; i += 256) dst[i] = src[i];
    }

    // ---- path score: unary + binary (masked by seq_len) ----
    float sc = 0.0f;
    for (int t = u; t < L; t += 256) {
        int tg = __ldg(&tags[b * TT + t]);
        sc += __ldg(&pot[(b * TT + t) * UU + tg]);
        if (t >= 1) {
            int tp = __ldg(&tags[b * TT + t - 1]);
            sc += __ldg(&trans[tp * UU + tg]);
        }
    }
    #pragma unroll
    for (int o = 16; o; o >>= 1) sc += __shfl_xor_sync(0xffffffffu, sc, o);
    if (lane == 0) red[wid] = sc;
    __syncthreads();
    if (u == 0) {
        float s = (red[0] + red[1]) + (red[2] + red[3])
                + (red[4] + red[5]) + (red[6] + red[7]);
        *sscore = s;
    }

    // ---- forward recursion ----
    float alpha = pot[b * TT * UU + u];    // alpha_0 = potentials[b,0,:]
    __syncthreads();                       // red reads (above) done; safe to reuse
    if (u == 0) *cscale = alpha;           // rough scale C (alpha spread << exp range)
    __syncthreads();

    const uint4* rp = (const uint4*)(Es + u * PITCH);

    for (int t = 1; t < L; t++) {
        float pot_t = __ldg(&pot[(b * TT + t) * UU + u]);   // prefetch (consumed at end)
        float C = *cscale;
        float e = __expf(alpha - C);

        // block sum A = sum_v ea[v] (single reduction; ea published same barrier)
        float ws = e;
        #pragma unroll
        for (int o = 16; o; o >>= 1) ws += __shfl_xor_sync(0xffffffffu, ws, o);
        if (lane == 0) red[wid] = ws;
        ea[u] = e;
        __syncthreads();
        float A = (red[0] + red[1]) + (red[2] + red[3])
                + (red[4] + red[5]) + (red[6] + red[7]);

        // S_u = A + sum_v ea[v] * (exp(trans[v,u]) - 1)   [bf16 Em1, fp32 accum]
        float s0 = 0.0f, s1 = 0.0f;
        #pragma unroll 4
        for (int v8 = 0; v8 < UU / 8; v8++) {
            uint4  w  = rp[v8];
            float4 a0 = *(const float4*)&ea[v8 * 8];
            float4 a1 = *(const float4*)&ea[v8 * 8 + 4];
            // bf16 -> f32 via bit shift (ALU pipe, no CVT)
            s0 += a0.x * __uint_as_float(w.x << 16);
            s1 += a0.y * __uint_as_float(w.x & 0xffff0000u);
            s0 += a0.z * __uint_as_float(w.y << 16);
            s1 += a0.w * __uint_as_float(w.y & 0xffff0000u);
            s0 += a1.x * __uint_as_float(w.z << 16);
            s1 += a1.y * __uint_as_float(w.z & 0xffff0000u);
            s0 += a1.z * __uint_as_float(w.w << 16);
            s1 += a1.w * __uint_as_float(w.w & 0xffff0000u);
        }
        alpha = C + __logf(A + s0 + s1) + pot_t;

        if (u == 0) *cscale = alpha;   // next step's scale (written before barrier)
        __syncthreads();               // ea/red/cscale hazards closed: 2 bars/step
    }

    // ---- log_norm = logsumexp(alpha) ----
    float m = alpha;
    #pragma unroll
    for (int o = 16; o; o >>= 1) m = fmaxf(m, __shfl_xor_sync(0xffffffffu, m, o));
    if (lane == 0) red[wid] = m;
    __syncthreads();
    m = fmaxf(fmaxf(fmaxf(red[0], red[1]), fmaxf(red[2], red[3])),
              fmaxf(fmaxf(red[4], red[5]), fmaxf(red[6], red[7])));
    __syncthreads();
    float ee = __expf(alpha - m);
    #pragma unroll
    for (int o = 16; o; o >>= 1) ee += __shfl_xor_sync(0xffffffffu, ee, o);
    if (lane == 0) red[wid] = ee;
    __syncthreads();
    if (u == 0) {
        float s = (red[0] + red[1]) + (red[2] + red[3])
                + (red[4] + red[5]) + (red[6] + red[7]);
        float logZ = m + __logf(s);
        g_ll[b] = *sscore - logZ;
    }
}

// ---------------------------------------------------------------------------
// Kernel 2: out = -mean(ll)
// ---------------------------------------------------------------------------
__global__ void k_final(float* __restrict__ out) {
    __shared__ float r[2];
    float v = g_ll[threadIdx.x];   // 64 threads
    #pragma unroll
    for (int o = 16; o; o >>= 1) v += __shfl_xor_sync(0xffffffffu, v, o);
    if ((threadIdx.x & 31) == 0) r[threadIdx.x >> 5] = v;
    __syncthreads();
    if (threadIdx.x == 0) out[0] = -(r[0] + r[1]) * (1.0f / (float)BB);
}

// ---------------------------------------------------------------------------
extern "C" void kernel_launch(void* const* d_in, const int* in_sizes, int n_in,
                              void* d_out, int out_size) {
    (void)in_sizes; (void)n_in; (void)out_size;
    const float* pot    = (const float*)d_in[0];
    const int*   tags   = (const int*)  d_in[1];
    const int*   seqlen = (const int*)  d_in[2];
    const float* trans  = (const float*)d_in[3];
    float* out = (float*)d_out;

    const int smem_bytes = UU * PITCH * 2 + (UU + 8 + 1 + 1) * (int)sizeof(float);
    cudaFuncSetAttribute(k_forward, cudaFuncAttributeMaxDynamicSharedMemorySize, smem_bytes);

    k_prep<<<UU, UU>>>(trans);
    k_forward<<<BB, UU, smem_bytes>>>(pot, tags, seqlen, trans);
    k_final<<<1, BB>>>(out);
}

// round 5
// speedup vs baseline: 1.7542x; 1.7542x over previous
#include <cuda_runtime.h>
#include <stdint.h>

#define BB 64
#define TT 512
#define UU 256
#define VH 128   // v-columns per CTA (cluster of 2 CTAs per batch)

__device__ float g_ll[BB];

// ---------------------------------------------------------------------------
// helpers
// ---------------------------------------------------------------------------
__device__ __forceinline__ uint32_t s2u(const void* p) {
    uint32_t r;
    asm("{ .reg .u64 t; cvta.to.shared.u64 t, %1; cvt.u32.u64 %0, t; }" : "=r"(r) : "l"(p));
    return r;
}
__device__ __forceinline__ unsigned long long pack2(float lo, float hi) {
    unsigned long long r;
    asm("mov.b64 %0, {%1, %2};" : "=l"(r) : "f"(lo), "f"(hi));
    return r;
}

struct __align__(16) Smem {
    float ea[UU];          // exp(alpha - C), indexed by v (==u)
    float recv[2][UU];     // peer partial sums, double-buffered (1KB stride)
    float calpha;          // broadcast of alpha[0] at init
    float pl0;             // thread0's local partial P (for redundant C update)
    float spot;            // pot[b,t,0]
    unsigned long long mb[2];  // mbarriers (peer arrives; count=1)
    float red[8];
    float sscore;
};

// ---------------------------------------------------------------------------
// k_forward: one 2-CTA cluster per batch; CTA rank r owns v in [r*128,(r+1)*128)
// Thread = u (0..255). E[v][u] for my v-half lives in 64 packed-f32x2 registers.
// Both CTAs compute the full alpha redundantly (S = P_mine + P_peer is
// commutative -> bitwise identical in both CTAs), exchanging 1KB of partials
// per step over DSMEM with a 2-deep mbarrier ring.
// ---------------------------------------------------------------------------
__global__ __launch_bounds__(256, 1) __cluster_dims__(2, 1, 1)
void k_forward(const float* __restrict__ pot,     // [B,T,U]
               const int*   __restrict__ tags,    // [B,T]
               const int*   __restrict__ seqlen,  // [B]
               const float* __restrict__ trans)   // [U,U]
{
    __shared__ Smem sm;
    const int u    = threadIdx.x;
    const int rank = blockIdx.x & 1;
    const int b    = blockIdx.x >> 1;
    const int lane = u & 31;
    const int wid  = u >> 5;
    const int L    = seqlen[b];

    // ---- mbarrier init (count=1: single release-arrive from peer's u0) ----
    if (u == 0) {
        asm volatile("mbarrier.init.shared.b64 [%0], 1;" :: "r"(s2u(&sm.mb[0])) : "memory");
        asm volatile("mbarrier.init.shared.b64 [%0], 1;" :: "r"(s2u(&sm.mb[1])) : "memory");
    }
    __syncthreads();
    asm volatile("barrier.cluster.arrive.aligned;" ::: "memory");

    // ---- load E[v][u] = exp(trans[v][u]) for my v-half into 64 f32x2 regs ----
    unsigned long long em[VH / 2];
    {
        const float* tb = trans + rank * VH * UU + u;   // column u, rows = my v-half
        #pragma unroll
        for (int j = 0; j < VH / 2; j++) {
            float f0 = __expf(__ldg(tb + (2 * j) * UU));
            float f1 = __expf(__ldg(tb + (2 * j + 1) * UU));
            em[j] = pack2(f0, f1);
        }
    }

    // finish cluster barrier (peer mbarriers initialized before any arrive)
    asm volatile("barrier.cluster.wait.aligned;" ::: "memory");

    // ---- path score (rank 0 only; CTA-uniform branch) ----
    if (rank == 0) {
        float sc = 0.0f;
        for (int t = u; t < L; t += 256) {
            int tg = __ldg(&tags[b * TT + t]);
            sc += __ldg(&pot[(b * TT + t) * UU + tg]);
            if (t >= 1) {
                int tp = __ldg(&tags[b * TT + t - 1]);
                sc += __ldg(&trans[tp * UU + tg]);
            }
        }
        #pragma unroll
        for (int o = 16; o; o >>= 1) sc += __shfl_xor_sync(0xffffffffu, sc, o);
        if (lane == 0) sm.red[wid] = sc;
        __syncthreads();
        if (u == 0)
            sm.sscore = (sm.red[0] + sm.red[1]) + (sm.red[2] + sm.red[3])
                      + (sm.red[4] + sm.red[5]) + (sm.red[6] + sm.red[7]);
    }

    // ---- alpha init + scale C (identical in both CTAs) ----
    float alpha = pot[b * TT * UU + u];
    if (u == 0) sm.calpha = alpha;
    __syncthreads();
    float C = sm.calpha;

    // hoisted addresses
    const uint32_t ea_base = s2u(&sm.ea[0]) + (uint32_t)(rank * VH) * 4u;
    const uint32_t l_mb    = s2u(&sm.mb[0]);
    const uint32_t l_recvu = s2u(&sm.recv[0][0]) + (uint32_t)u * 4u;
    const uint32_t l_recv0 = s2u(&sm.recv[0][0]);
    uint32_t r_recvu, r_mb;
    asm("mapa.shared::cluster.u32 %0, %1, %2;" : "=r"(r_recvu)
        : "r"(l_recvu), "r"(rank ^ 1));
    asm("mapa.shared::cluster.u32 %0, %1, %2;" : "=r"(r_mb) : "r"(l_mb), "r"(rank ^ 1));

    // ---- forward recursion ----
    // ring state: buf alternates 0,1; each barrier is used every 2 steps and
    // must see alternating parity per *use*: flip par when wrapping to buf 0.
    uint32_t bufoff = 0;          // buf * 1024 bytes (recv row stride)
    uint32_t mboff  = 0;          // buf * 8 bytes
    uint32_t par    = 0;          // phase parity for current buf
    for (int t = 1; t < L; t++) {
        float pot_t = __ldg(&pot[(b * TT + t) * UU + u]);   // consumed at end
        float e = __expf(alpha - C);
        sm.ea[u] = e;
        __syncthreads();                                    // bar1: ea published

        // partial S over my v-half: P_u = sum_v ea[v] * E[v][u]  (f32x2 packed)
        unsigned long long acc0 = 0ull, acc1 = 0ull;
        #pragma unroll
        for (int i = 0; i < VH / 4; i++) {                  // 32 iters: 4 v each
            unsigned long long a0, a1;
            asm volatile("ld.shared.v2.u64 {%0, %1}, [%2];"
                         : "=l"(a0), "=l"(a1) : "r"(ea_base + 16u * i));
            asm("fma.rn.f32x2 %0, %1, %2, %0;" : "+l"(acc0) : "l"(a0), "l"(em[2 * i]));
            asm("fma.rn.f32x2 %0, %1, %2, %0;" : "+l"(acc1) : "l"(a1), "l"(em[2 * i + 1]));
        }
        unsigned long long accs;
        asm("add.rn.f32x2 %0, %1, %2;" : "=l"(accs) : "l"(acc0), "l"(acc1));
        float plo, phi;
        asm("mov.b64 {%0, %1}, %2;" : "=f"(plo), "=f"(phi) : "l"(accs));
        float P = plo + phi;

        // publish partial to peer recv[buf][u] + local aux slots
        asm volatile("st.shared::cluster.f32 [%0], %1;"
                     :: "r"(r_recvu + bufoff), "f"(P) : "memory");
        if (u == 0) { sm.pl0 = P; sm.spot = pot_t; }
        __syncthreads();                                    // bar2: all sts done (hb to u0)

        if (u == 0)
            asm volatile("mbarrier.arrive.release.cluster.shared::cluster.b64 _, [%0];"
                         :: "r"(r_mb + mboff) : "memory");

        // wait for peer's arrival on my mb[buf] (acquire, cluster scope)
        {
            uint32_t done = 0;
            while (!done) {
                asm volatile(
                    "{ .reg .pred p;\n\t"
                    "mbarrier.try_wait.parity.acquire.cluster.shared::cta.b64 p, [%1], %2, 0x989680;\n\t"
                    "selp.b32 %0, 1, 0, p; }"
                    : "=r"(done) : "r"(l_mb + mboff), "r"(par) : "memory");
            }
        }

        float R, R0;
        asm("ld.shared.f32 %0, [%1];" : "=f"(R)  : "r"(l_recvu + bufoff));
        asm("ld.shared.f32 %0, [%1];" : "=f"(R0) : "r"(l_recv0 + bufoff));
        float S = P + R;                                     // commutative: identical in both CTAs
        float newC = C + __logf(sm.pl0 + R0) + sm.spot;      // == new alpha[0], redundant
        alpha = C + __logf(S) + pot_t;
        C = newC;

        // advance ring
        par    ^= (bufoff >> 10);          // wrapping from buf 1 -> flip parity
        bufoff ^= 1024u;
        mboff  ^= 8u;
    }

    // all exchange traffic complete before any CTA exits
    asm volatile("barrier.cluster.arrive.aligned;" ::: "memory");
    asm volatile("barrier.cluster.wait.aligned;" ::: "memory");

    // ---- finalize: logsumexp(alpha) - score (rank 0 only) ----
    if (rank == 0) {
        float m = alpha;
        #pragma unroll
        for (int o = 16; o; o >>= 1) m = fmaxf(m, __shfl_xor_sync(0xffffffffu, m, o));
        if (lane == 0) sm.red[wid] = m;
        __syncthreads();
        m = fmaxf(fmaxf(fmaxf(sm.red[0], sm.red[1]), fmaxf(sm.red[2], sm.red[3])),
                  fmaxf(fmaxf(sm.red[4], sm.red[5]), fmaxf(sm.red[6], sm.red[7])));
        __syncthreads();
        float ee = __expf(alpha - m);
        #pragma unroll
        for (int o = 16; o; o >>= 1) ee += __shfl_xor_sync(0xffffffffu, ee, o);
        if (lane == 0) sm.red[wid] = ee;
        __syncthreads();
        if (u == 0) {
            float s = (sm.red[0] + sm.red[1]) + (sm.red[2] + sm.red[3])
                    + (sm.red[4] + sm.red[5]) + (sm.red[6] + sm.red[7]);
            g_ll[b] = sm.sscore - (m + __logf(s));
        }
    }
}

// ---------------------------------------------------------------------------
// k_final: out = -mean(ll)
// ---------------------------------------------------------------------------
__global__ void k_final(float* __restrict__ out) {
    __shared__ float r[2];
    float v = g_ll[threadIdx.x];   // 64 threads
    #pragma unroll
    for (int o = 16; o; o >>= 1) v += __shfl_xor_sync(0xffffffffu, v, o);
    if ((threadIdx.x & 31) == 0) r[threadIdx.x >> 5] = v;
    __syncthreads();
    if (threadIdx.x == 0) out[0] = -(r[0] + r[1]) * (1.0f / (float)BB);
}

// ---------------------------------------------------------------------------
extern "C" void kernel_launch(void* const* d_in, const int* in_sizes, int n_in,
                              void* d_out, int out_size) {
    (void)in_sizes; (void)n_in; (void)out_size;
    const float* pot    = (const float*)d_in[0];
    const int*   tags   = (const int*)  d_in[1];
    const int*   seqlen = (const int*)  d_in[2];
    const float* trans  = (const float*)d_in[3];
    float* out = (float*)d_out;

    k_forward<<<BB * 2, UU>>>(pot, tags, seqlen, trans);   // 64 clusters of 2 CTAs
    k_final<<<1, BB>>>(out);
}